// round 3
// baseline (speedup 1.0000x reference)
#include <cuda_runtime.h>

#define NB   64
#define TT   12
#define NN   325
#define HH   64
#define EE   32
#define LHH  128
#define NOUT 12
#define XST  97      // 1 + 64 + 32
#define MOFF 65

#define ROWS 64      // rows per CTA
#define RPW  8       // rows per warp (8 warps)
#define NCHUNK 6     // ceil(325/64)

// ---------------- device scratch ----------------
__device__ float g_meta[NB * EE];
__device__ float g_hidden[3 * 4 * NB * LHH];
__device__ float g_Wx[4 * NB * HH];
__device__ float g_bg[4 * NB * HH];
__device__ float g_Wh[4 * NB * HH * HH];

// ---------------- packed fp32x2 helpers ----------------
__device__ __forceinline__ unsigned long long pk2(float a) {
    unsigned long long d;
    unsigned int u = __float_as_uint(a);
    asm("mov.b64 %0, {%1, %2};" : "=l"(d) : "r"(u), "r"(u));
    return d;
}
__device__ __forceinline__ unsigned long long fma2v(unsigned long long a,
                                                    unsigned long long b,
                                                    unsigned long long c) {
    unsigned long long d;
    asm("fma.rn.f32x2 %0, %1, %2, %3;" : "=l"(d) : "l"(a), "l"(b), "l"(c));
    return d;
}
__device__ __forceinline__ void upk(unsigned long long v, float& lo, float& hi) {
    unsigned int a, b;
    asm("mov.b64 {%0, %1}, %2;" : "=r"(a), "=r"(b) : "l"(v));
    lo = __uint_as_float(a); hi = __uint_as_float(b);
}

// ---------------- fast activations (MUFU) ----------------
__device__ __forceinline__ float ex2f(float x) {
    float y; asm("ex2.approx.f32 %0,%1;" : "=f"(y) : "f"(x)); return y;
}
__device__ __forceinline__ float rcpf(float x) {
    float y; asm("rcp.approx.f32 %0,%1;" : "=f"(y) : "f"(x)); return y;
}
__device__ __forceinline__ float sig_a(float z) {
    return rcpf(1.0f + ex2f(-1.4426950408889634f * z));
}
__device__ __forceinline__ float tanh_a(float z) {
    return fmaf(-2.0f, rcpf(1.0f + ex2f(2.8853900817779268f * z)), 1.0f);
}

// ---------------- K1: meta mean ----------------
__global__ void k_meta(const float* __restrict__ x) {
    int b = blockIdx.x, e = threadIdx.x;
    float s = 0.f;
    #pragma unroll
    for (int t = 0; t < TT; t++)
        s += x[((size_t)(b * TT + t) * NN + 0) * XST + MOFF + e];
    g_meta[b * EE + e] = s * (1.0f / TT);
}

// ---------------- K2: first MLP layers ----------------
__global__ void k_hidden(const float* __restrict__ xW1, const float* __restrict__ xb1,
                         const float* __restrict__ hW1, const float* __restrict__ hb1,
                         const float* __restrict__ bW1, const float* __restrict__ bb1) {
    int b = blockIdx.x, g = blockIdx.y, m = blockIdx.z;
    int l = threadIdx.x;
    const float* W1 = (m == 0) ? xW1 : (m == 1) ? hW1 : bW1;
    const float* b1 = (m == 0) ? xb1 : (m == 1) ? hb1 : bb1;
    float acc = b1[g * LHH + l];
    #pragma unroll 8
    for (int e = 0; e < EE; e++)
        acc = fmaf(g_meta[b * EE + e], W1[(g * EE + e) * LHH + l], acc);
    g_hidden[((m * 4 + g) * NB + b) * LHH + l] = fmaxf(acc, 0.f);
}

// ---------------- K3ab: Wx and bias second layers ----------------
__global__ void k_small2(const float* __restrict__ xW2, const float* __restrict__ xb2,
                         const float* __restrict__ bW2, const float* __restrict__ bb2) {
    int b = blockIdx.x, g = blockIdx.y, m2 = blockIdx.z;
    int k = threadIdx.x;
    int m = (m2 == 0) ? 0 : 2;
    const float* W2 = (m2 == 0) ? xW2 : bW2;
    const float* b2 = (m2 == 0) ? xb2 : bb2;
    const float* hid = &g_hidden[((m * 4 + g) * NB + b) * LHH];
    float acc = b2[g * HH + k];
    #pragma unroll 8
    for (int l = 0; l < LHH; l++)
        acc = fmaf(hid[l], W2[(g * LHH + l) * HH + k], acc);
    float* dst = (m2 == 0) ? g_Wx : g_bg;
    dst[(g * NB + b) * HH + k] = acc;
}

// ---------------- K3c: Wh second layer GEMM ----------------
__global__ void k_wh2(const float* __restrict__ hW2, const float* __restrict__ hb2) {
    __shared__ float hs[8][LHH];
    int kchunk = blockIdx.x, btile = blockIdx.y, g = blockIdx.z;
    int tid = threadIdx.x;          // 256
    int k = kchunk * 256 + tid;
    for (int i = tid; i < 8 * LHH; i += 256) {
        int bb = i >> 7, l = i & 127;
        hs[bb][l] = g_hidden[((4 + g) * NB + (btile * 8 + bb)) * LHH + l];
    }
    __syncthreads();
    float acc[8];
    #pragma unroll
    for (int bb = 0; bb < 8; bb++) acc[bb] = 0.f;
    #pragma unroll 8
    for (int l = 0; l < LHH; l++) {
        float w = hW2[(g * LHH + l) * 4096 + k];
        #pragma unroll
        for (int bb = 0; bb < 8; bb++) acc[bb] = fmaf(hs[bb][l], w, acc[bb]);
    }
    float bias = hb2[g * 4096 + k];
    #pragma unroll
    for (int bb = 0; bb < 8; bb++)
        g_Wh[(g * NB + (btile * 8 + bb)) * 4096 + k] = acc[bb] + bias;
}

// ---------------- K4: fused LSTM recurrence + FC head ----------------
// dynamic smem layout (float offsets)
#define OFF_WA   0                      // 2048 float4 = 8192 floats (gates 0,1)
#define OFF_WB   8192                   // 8192 floats (gates 2,3)
#define OFF_WX   16384                  // 256
#define OFF_BG   16640                  // 256
#define OFF_H    16896                  // 64*64 = 4096
#define OFF_CS   20992                  // 64*64 = 4096  (cell state)
#define OFF_XS   25088                  // 64*12 = 768
#define OFF_FC1  25856                  // 2048
#define OFF_FC2  27904                  // 384
#define OFF_F1B  28288                  // 32
#define OFF_F2B  28320                  // 16 (pad)
#define OFF_MID  28336                  // 256
#define SMEM_FLOATS 28592
#define SMEM_BYTES (SMEM_FLOATS * 4)    // 114368 B -> 2 CTAs/SM fits 228KB

__global__ __launch_bounds__(256, 2)
void k_lstm(const float* __restrict__ x,
            const float* __restrict__ fc1W, const float* __restrict__ fc1b,
            const float* __restrict__ fc2W, const float* __restrict__ fc2b,
            float* __restrict__ out) {
    extern __shared__ float sm[];
    float4* wA4 = (float4*)(sm + OFF_WA);
    float4* wB4 = (float4*)(sm + OFF_WB);
    float* wxs  = sm + OFF_WX;
    float* bgs  = sm + OFF_BG;
    float* hs   = sm + OFF_H;
    float* cs   = sm + OFF_CS;
    float* xss  = sm + OFF_XS;
    float* fc1s = sm + OFF_FC1;
    float* fc2s = sm + OFF_FC2;
    float* f1bs = sm + OFF_F1B;
    float* f2bs = sm + OFF_F2B;
    float* mids = sm + OFF_MID;

    int chunk = blockIdx.x, b = blockIdx.y;
    int tid = threadIdx.x;
    int n0 = chunk * ROWS;

    // ---- stage packed Wh: wA4[j*32+l] = {g0[k0],g0[k1],g1[k0],g1[k1]} ----
    for (int i = tid; i < 2048; i += 256) {
        int j = i >> 5, l = i & 31;
        const float* p = &g_Wh[(size_t)b * 4096 + j * 64 + 2 * l];
        float2 a0 = *(const float2*)(p);
        float2 a1 = *(const float2*)(p + (size_t)NB * 4096);
        float2 a2 = *(const float2*)(p + (size_t)2 * NB * 4096);
        float2 a3 = *(const float2*)(p + (size_t)3 * NB * 4096);
        wA4[i] = make_float4(a0.x, a0.y, a1.x, a1.y);
        wB4[i] = make_float4(a2.x, a2.y, a3.x, a3.y);
    }
    {
        int g = tid >> 6, k = tid & 63;
        wxs[tid] = g_Wx[(g * NB + b) * HH + k];
        bgs[tid] = g_bg[(g * NB + b) * HH + k];
    }
    for (int i = tid; i < ROWS * TT; i += 256) {
        int r = i / TT, t = i % TT;
        int n = n0 + r;
        xss[r * TT + t] = (n < NN) ? x[((size_t)(b * TT + t) * NN + n) * XST] : 0.f;
    }
    for (int i = tid; i < HH * 32; i += 256) fc1s[i] = fc1W[i];
    for (int i = tid; i < 32 * NOUT; i += 256) fc2s[i] = fc2W[i];
    if (tid < 32) f1bs[tid] = fc1b[tid];
    if (tid < NOUT) f2bs[tid] = fc2b[tid];
    __syncthreads();

    int w = tid >> 5, l = tid & 31;
    int k0 = 2 * l;
    const int row0 = w * RPW;

    unsigned long long wxu[4], blu[4];
    #pragma unroll
    for (int g = 0; g < 4; g++) {
        wxu[g] = *(const unsigned long long*)&wxs[g * HH + k0];
        blu[g] = *(const unsigned long long*)&bgs[g * HH + k0];
    }

    // ---- t = 0: h=c=0, so z = x*wx + b exactly ----
    #pragma unroll
    for (int r = 0; r < RPW; r++) {
        int row = row0 + r;
        unsigned long long xp = pk2(xss[row * TT]);
        float zg0, zg1, zi0, zi1, zf0, zf1, zo0, zo1;
        upk(fma2v(xp, wxu[0], blu[0]), zg0, zg1);
        upk(fma2v(xp, wxu[1], blu[1]), zi0, zi1);
        upk(fma2v(xp, wxu[2], blu[2]), zf0, zf1);
        upk(fma2v(xp, wxu[3], blu[3]), zo0, zo1);
        (void)zf0; (void)zf1;
        float c0 = tanh_a(zg0) * sig_a(zi0);
        float c1 = tanh_a(zg1) * sig_a(zi1);
        *(float2*)&cs[row * HH + k0] = make_float2(c0, c1);
        *(float2*)&hs[row * HH + k0] = make_float2(tanh_a(c0) * sig_a(zo0),
                                                   tanh_a(c1) * sig_a(zo1));
    }
    __syncwarp();

    // ---- t = 1..11 ----
    for (int t = 1; t < TT; t++) {
        unsigned long long acc[RPW][4];
        #pragma unroll
        for (int r = 0; r < RPW; r++) {
            unsigned long long xp = pk2(xss[(row0 + r) * TT + t]);
            #pragma unroll
            for (int g = 0; g < 4; g++)
                acc[r][g] = fma2v(xp, wxu[g], blu[g]);
        }

        #pragma unroll 2
        for (int j2 = 0; j2 < HH; j2 += 2) {
            float2 h2[RPW];
            #pragma unroll
            for (int r = 0; r < RPW; r++)
                h2[r] = *(const float2*)&hs[(row0 + r) * HH + j2];
            #pragma unroll
            for (int jj = 0; jj < 2; jj++) {
                ulonglong2 wa = *(const ulonglong2*)&wA4[(j2 + jj) * 32 + l];
                ulonglong2 wb = *(const ulonglong2*)&wB4[(j2 + jj) * 32 + l];
                #pragma unroll
                for (int r = 0; r < RPW; r++) {
                    float hj = jj ? h2[r].y : h2[r].x;
                    unsigned long long hh = pk2(hj);
                    acc[r][0] = fma2v(hh, wa.x, acc[r][0]);
                    acc[r][1] = fma2v(hh, wa.y, acc[r][1]);
                    acc[r][2] = fma2v(hh, wb.x, acc[r][2]);
                    acc[r][3] = fma2v(hh, wb.y, acc[r][3]);
                }
            }
        }
        __syncwarp();   // all lanes done reading hs for this step

        #pragma unroll
        for (int r = 0; r < RPW; r++) {
            int row = row0 + r;
            float zg0, zg1, zi0, zi1, zf0, zf1, zo0, zo1;
            upk(acc[r][0], zg0, zg1);
            upk(acc[r][1], zi0, zi1);
            upk(acc[r][2], zf0, zf1);
            upk(acc[r][3], zo0, zo1);
            float2 cv = *(const float2*)&cs[row * HH + k0];
            float c0 = fmaf(cv.x, sig_a(zf0), tanh_a(zg0) * sig_a(zi0));
            float c1 = fmaf(cv.y, sig_a(zf1), tanh_a(zg1) * sig_a(zi1));
            *(float2*)&cs[row * HH + k0] = make_float2(c0, c1);
            *(float2*)&hs[row * HH + k0] = make_float2(tanh_a(c0) * sig_a(zo0),
                                                       tanh_a(c1) * sig_a(zo1));
        }
        __syncwarp();   // writes visible before next step's reads
    }

    // ---- FC head: relu(h) -> 32 (relu) -> 12 ----
    #pragma unroll
    for (int r = 0; r < RPW; r++) {
        int row = row0 + r;
        int n = n0 + row;
        float m = f1bs[l];
        #pragma unroll 8
        for (int j = 0; j < HH; j++)
            m = fmaf(fmaxf(hs[row * HH + j], 0.f), fc1s[j * 32 + l], m);
        m = fmaxf(m, 0.f);
        mids[w * 32 + l] = m;
        __syncwarp();
        if (l < NOUT) {
            float o = f2bs[l];
            #pragma unroll
            for (int q = 0; q < 32; q++)
                o = fmaf(mids[w * 32 + q], fc2s[q * NOUT + l], o);
            if (n < NN) out[(b * NOUT + l) * NN + n] = o;
        }
        __syncwarp();
    }
}

// ---------------- launch ----------------
extern "C" void kernel_launch(void* const* d_in, const int* in_sizes, int n_in,
                              void* d_out, int out_size) {
    const float* x      = (const float*)d_in[0];
    const float* lwx_W1 = (const float*)d_in[1];
    const float* lwx_b1 = (const float*)d_in[2];
    const float* lwx_W2 = (const float*)d_in[3];
    const float* lwx_b2 = (const float*)d_in[4];
    const float* lwh_W1 = (const float*)d_in[5];
    const float* lwh_b1 = (const float*)d_in[6];
    const float* lwh_W2 = (const float*)d_in[7];
    const float* lwh_b2 = (const float*)d_in[8];
    const float* lb_W1  = (const float*)d_in[9];
    const float* lb_b1  = (const float*)d_in[10];
    const float* lb_W2  = (const float*)d_in[11];
    const float* lb_b2  = (const float*)d_in[12];
    const float* fc1_W  = (const float*)d_in[13];
    const float* fc1_b  = (const float*)d_in[14];
    const float* fc2_W  = (const float*)d_in[15];
    const float* fc2_b  = (const float*)d_in[16];
    float* out = (float*)d_out;

    cudaFuncSetAttribute(k_lstm, cudaFuncAttributeMaxDynamicSharedMemorySize, SMEM_BYTES);

    k_meta<<<NB, EE>>>(x);
    k_hidden<<<dim3(NB, 4, 3), LHH>>>(lwx_W1, lwx_b1, lwh_W1, lwh_b1, lb_W1, lb_b1);
    k_small2<<<dim3(NB, 4, 2), HH>>>(lwx_W2, lwx_b2, lb_W2, lb_b2);
    k_wh2<<<dim3(16, 8, 4), 256>>>(lwh_W2, lwh_b2);
    k_lstm<<<dim3(NCHUNK, NB), 256, SMEM_BYTES>>>(x, fc1_W, fc1_b, fc2_W, fc2_b, out);
}

// round 5
// speedup vs baseline: 1.1301x; 1.1301x over previous
#include <cuda_runtime.h>
#include <cuda_bf16.h>
#include <cstdint>

#define NB   64
#define TT   12
#define NN   325
#define HH   64
#define EE   32
#define LHH  128
#define NOUT 12
#define XST  97
#define MOFF 65

#define MROWS 64
#define NCHUNK 6                 // ceil(325/64)
#define NKT   5                  // k-tiles of 16 over augmented K=80

typedef unsigned long long ull;

// ---------------- device scratch ----------------
__device__ float g_meta[NB * EE];
__device__ float g_hidden[3 * 4 * NB * LHH];
__device__ float g_Wx[4 * NB * HH];
__device__ float g_bg[4 * NB * HH];
__device__ float g_Wh[4 * NB * HH * HH];
__device__ __align__(16) ull g_WBH[NB * NKT * 32 * 32];   // B fragments (hi)
__device__ __align__(16) ull g_WBL[NB * NKT * 32 * 32];   // B fragments (lo)

// ---------------- activations ----------------
__device__ __forceinline__ float ex2f(float x) {
    float y; asm("ex2.approx.f32 %0,%1;" : "=f"(y) : "f"(x)); return y;
}
__device__ __forceinline__ float rcpf(float x) {
    float y; asm("rcp.approx.f32 %0,%1;" : "=f"(y) : "f"(x)); return y;
}
__device__ __forceinline__ float sig_a(float z) {
    return rcpf(1.0f + ex2f(-1.4426950408889634f * z));
}
__device__ __forceinline__ float tanh_a(float z) {
    return fmaf(-2.0f, rcpf(1.0f + ex2f(2.8853900817779268f * z)), 1.0f);
}

// ---------------- mma.sync m16n8k16 bf16 (legacy HMMA, sm_80 baseline) ----
__device__ __forceinline__ void mma16816(float* c,
    uint32_t a0, uint32_t a1, uint32_t a2, uint32_t a3,
    uint32_t b0, uint32_t b1) {
    asm volatile(
        "mma.sync.aligned.m16n8k16.row.col.f32.bf16.bf16.f32 "
        "{%0,%1,%2,%3}, {%4,%5,%6,%7}, {%8,%9}, {%0,%1,%2,%3};"
        : "+f"(c[0]), "+f"(c[1]), "+f"(c[2]), "+f"(c[3])
        : "r"(a0), "r"(a1), "r"(a2), "r"(a3), "r"(b0), "r"(b1));
}
__device__ __forceinline__ uint32_t lo32(ull v) { return (uint32_t)v; }
__device__ __forceinline__ uint32_t hi32(ull v) { return (uint32_t)(v >> 32); }

// ---------------- K1: meta ----------------
__global__ void k_meta(const float* __restrict__ x) {
    int b = blockIdx.x, e = threadIdx.x;
    float s = 0.f;
    #pragma unroll
    for (int t = 0; t < TT; t++)
        s += x[((size_t)(b * TT + t) * NN) * XST + MOFF + e];
    g_meta[b * EE + e] = s * (1.0f / TT);
}

// ---------------- K2: first MLP layers ----------------
__global__ void k_hidden(const float* __restrict__ xW1, const float* __restrict__ xb1,
                         const float* __restrict__ hW1, const float* __restrict__ hb1,
                         const float* __restrict__ bW1, const float* __restrict__ bb1) {
    int b = blockIdx.x, g = blockIdx.y, m = blockIdx.z;
    int l = threadIdx.x;
    const float* W1 = (m == 0) ? xW1 : (m == 1) ? hW1 : bW1;
    const float* b1 = (m == 0) ? xb1 : (m == 1) ? hb1 : bb1;
    float acc = b1[g * LHH + l];
    #pragma unroll 8
    for (int e = 0; e < EE; e++)
        acc = fmaf(g_meta[b * EE + e], W1[(g * EE + e) * LHH + l], acc);
    g_hidden[((m * 4 + g) * NB + b) * LHH + l] = fmaxf(acc, 0.f);
}

// ---------------- K3ab: Wx / bias second layers ----------------
__global__ void k_small2(const float* __restrict__ xW2, const float* __restrict__ xb2,
                         const float* __restrict__ bW2, const float* __restrict__ bb2) {
    int b = blockIdx.x, g = blockIdx.y, m2 = blockIdx.z;
    int k = threadIdx.x;
    int m = (m2 == 0) ? 0 : 2;
    const float* W2 = (m2 == 0) ? xW2 : bW2;
    const float* b2 = (m2 == 0) ? xb2 : bb2;
    const float* hid = &g_hidden[((m * 4 + g) * NB + b) * LHH];
    float acc = b2[g * HH + k];
    #pragma unroll 8
    for (int l = 0; l < LHH; l++)
        acc = fmaf(hid[l], W2[(g * LHH + l) * HH + k], acc);
    float* dst = (m2 == 0) ? g_Wx : g_bg;
    dst[(g * NB + b) * HH + k] = acc;
}

// ---------------- K3c: Wh second layer GEMM ----------------
__global__ void k_wh2(const float* __restrict__ hW2, const float* __restrict__ hb2) {
    __shared__ float hs[8][LHH];
    int kq = blockIdx.x, bt = blockIdx.y, g = blockIdx.z;
    int tid = threadIdx.x;                   // 256
    for (int i = tid; i < 8 * LHH; i += 256) {
        int bb = i >> 7, l = i & 127;
        hs[bb][l] = g_hidden[((4 + g) * NB + (bt * 8 + bb)) * LHH + l];
    }
    __syncthreads();
    int k4 = kq * 1024 + tid * 4;
    float4 acc[8];
    #pragma unroll
    for (int bb = 0; bb < 8; bb++) acc[bb] = make_float4(0.f, 0.f, 0.f, 0.f);
    #pragma unroll 4
    for (int l = 0; l < LHH; l++) {
        float4 wv = *(const float4*)&hW2[(size_t)(g * LHH + l) * 4096 + k4];
        #pragma unroll
        for (int bb = 0; bb < 8; bb++) {
            float h = hs[bb][l];
            acc[bb].x = fmaf(h, wv.x, acc[bb].x);
            acc[bb].y = fmaf(h, wv.y, acc[bb].y);
            acc[bb].z = fmaf(h, wv.z, acc[bb].z);
            acc[bb].w = fmaf(h, wv.w, acc[bb].w);
        }
    }
    float4 bias = *(const float4*)&hb2[g * 4096 + k4];
    #pragma unroll
    for (int bb = 0; bb < 8; bb++) {
        float4 v = make_float4(acc[bb].x + bias.x, acc[bb].y + bias.y,
                               acc[bb].z + bias.z, acc[bb].w + bias.w);
        *(float4*)&g_Wh[(size_t)(g * NB + bt * 8 + bb) * 4096 + k4] = v;
    }
}

// ---------------- K3d: pack augmented WB into B-fragment layout ----------
// WB[j][col= g*64+kk]: j<64 -> Wh[g][j][kk]; j==64 -> Wx; j==65 -> bias; else 0
__device__ __forceinline__ float fetchWB(int b, int j, int col) {
    int g = col >> 6, kk = col & 63;
    if (j < 64)  return g_Wh[((size_t)(g * NB + b) << 12) + j * 64 + kk];
    if (j == 64) return g_Wx[(g * NB + b) * HH + kk];
    if (j == 65) return g_bg[(g * NB + b) * HH + kk];
    return 0.f;
}
__global__ void k_pack3() {
    int b = blockIdx.x, tid = threadIdx.x;
    for (int it = tid; it < NKT * 32 * 32; it += 256) {
        int L = it & 31, ntg = (it >> 5) & 31, kt = it >> 10;
        int col = ntg * 8 + (L >> 2);
        int j0 = kt * 16 + (L & 3) * 2;
        float v00 = fetchWB(b, j0,     col);
        float v01 = fetchWB(b, j0 + 1, col);
        float v10 = fetchWB(b, j0 + 8, col);
        float v11 = fetchWB(b, j0 + 9, col);
        __nv_bfloat16 h00 = __float2bfloat16_rn(v00);
        __nv_bfloat16 h01 = __float2bfloat16_rn(v01);
        __nv_bfloat16 h10 = __float2bfloat16_rn(v10);
        __nv_bfloat16 h11 = __float2bfloat16_rn(v11);
        uint32_t p0 = (uint32_t)__bfloat16_as_ushort(h00) |
                      ((uint32_t)__bfloat16_as_ushort(h01) << 16);
        uint32_t p1 = (uint32_t)__bfloat16_as_ushort(h10) |
                      ((uint32_t)__bfloat16_as_ushort(h11) << 16);
        g_WBH[(size_t)b * (NKT * 1024) + it] = (ull)p0 | ((ull)p1 << 32);
        __nv_bfloat16 l00 = __float2bfloat16_rn(v00 - __bfloat162float(h00));
        __nv_bfloat16 l01 = __float2bfloat16_rn(v01 - __bfloat162float(h01));
        __nv_bfloat16 l10 = __float2bfloat16_rn(v10 - __bfloat162float(h10));
        __nv_bfloat16 l11 = __float2bfloat16_rn(v11 - __bfloat162float(h11));
        uint32_t q0 = (uint32_t)__bfloat16_as_ushort(l00) |
                      ((uint32_t)__bfloat16_as_ushort(l01) << 16);
        uint32_t q1 = (uint32_t)__bfloat16_as_ushort(l10) |
                      ((uint32_t)__bfloat16_as_ushort(l11) << 16);
        g_WBL[(size_t)b * (NKT * 1024) + it] = (ull)q0 | ((ull)q1 << 32);
    }
}

// ---------------- K4: HMMA LSTM recurrence + FC head ----------------
// smem byte offsets (all 16B aligned)
#define SM_BH   0        // 5*32*32 u64 = 40960
#define SM_BL   40960    // 40960  (hF 16KB overlays after last MMA)
#define SM_AH   81920    // 4mt*5kt*2rh*32 u64 = 10240
#define SM_AL   92160    // 10240
#define SM_ZLO  102400   // 4mt*16nt*32 float2 = 16384
#define SM_ZHI  118784   // 16384
#define SM_XS   135168   // 64*12*4 = 3072
#define SM_FC1  138240   // 8192
#define SM_FC2  146432   // 1536
#define SM_F1B  147968   // 128
#define SM_F2B  148096   // 64
#define SM_MID  148160   // 1024
#define SM_TOT  149184

__global__ __launch_bounds__(256, 1)
void k_lstm3(const float* __restrict__ x,
             const float* __restrict__ fc1W, const float* __restrict__ fc1b,
             const float* __restrict__ fc2W, const float* __restrict__ fc2b,
             float* __restrict__ out) {
    extern __shared__ char smc[];
    ull*    BH  = (ull*)(smc + SM_BH);
    ull*    BL  = (ull*)(smc + SM_BL);
    ull*    AHs = (ull*)(smc + SM_AH);
    ull*    ALs = (ull*)(smc + SM_AL);
    float2* ZLO = (float2*)(smc + SM_ZLO);
    float2* ZHI = (float2*)(smc + SM_ZHI);
    float*  xs  = (float*)(smc + SM_XS);
    float*  fc1s = (float*)(smc + SM_FC1);
    float*  fc2s = (float*)(smc + SM_FC2);
    float*  f1bs = (float*)(smc + SM_F1B);
    float*  f2bs = (float*)(smc + SM_F2B);
    float*  mids = (float*)(smc + SM_MID);
    float*  hF  = (float*)(smc + SM_BL);   // overlay

    int chunk = blockIdx.x, b = blockIdx.y;
    int tid = threadIdx.x;
    int w = tid >> 5, L = tid & 31;
    int mt = w >> 1, half = w & 1;
    int n0 = chunk * MROWS;
    int rowp = mt * 16 + half * 8 + (L >> 2);   // row this lane updates

    // ---- stage ----
    {
        const ulonglong2* gH = (const ulonglong2*)&g_WBH[(size_t)b * (NKT * 1024)];
        const ulonglong2* gL = (const ulonglong2*)&g_WBL[(size_t)b * (NKT * 1024)];
        ulonglong2* dH = (ulonglong2*)BH;
        ulonglong2* dL = (ulonglong2*)BL;
        for (int i = tid; i < NKT * 512; i += 256) { dH[i] = gH[i]; dL[i] = gL[i]; }
    }
    for (int i = tid; i < 4 * NKT * 2 * 32; i += 256) { AHs[i] = 0ull; ALs[i] = 0ull; }
    for (int i = tid; i < MROWS * TT; i += 256) {
        int r = i / TT, t = i % TT;
        int n = n0 + r;
        xs[r * TT + t] = (n < NN) ? x[((size_t)(b * TT + t) * NN + n) * XST] : 0.f;
    }
    for (int i = tid; i < HH * 32; i += 256) fc1s[i] = fc1W[i];
    for (int i = tid; i < 32 * NOUT; i += 256) fc2s[i] = fc2W[i];
    if (tid < 32) f1bs[tid] = fc1b[tid];
    if (tid < NOUT) f2bs[tid] = fc2b[tid];
    __syncthreads();

    // seed augmented k-tile (kt=4) with x_0 and 1.0 (only lanes L%4==0 hold j64,j65)
    if ((L & 3) == 0) {
        float xv = xs[rowp * TT];
        __nv_bfloat16 xh = __float2bfloat16_rn(xv);
        float xr = xv - __bfloat162float(xh);
        uint32_t ph = (uint32_t)__bfloat16_as_ushort(xh) | (0x3F80u << 16);
        uint32_t pl = (uint32_t)__bfloat16_as_ushort(__float2bfloat16_rn(xr));
        AHs[((mt * NKT + 4) * 2 + half) * 32 + L] = (ull)ph;
        ALs[((mt * NKT + 4) * 2 + half) * 32 + L] = (ull)pl;
    }

    float cst[16];
    #pragma unroll
    for (int i = 0; i < 16; i++) cst[i] = 0.f;

    for (int t = 0; t < TT; t++) {
        __syncthreads();   // A-frags (h_{t-1}, x_t) visible to MMA

        float acc[16][4];
        #pragma unroll
        for (int nt = 0; nt < 16; nt++)
            #pragma unroll
            for (int i = 0; i < 4; i++) acc[nt][i] = 0.f;

        #pragma unroll
        for (int kt = 0; kt < NKT; kt++) {
            if (t == 0 && kt < 4) continue;      // h=0 at t=0
            ull ah0 = AHs[((mt * NKT + kt) * 2 + 0) * 32 + L];
            ull ah1 = AHs[((mt * NKT + kt) * 2 + 1) * 32 + L];
            ull al0 = ALs[((mt * NKT + kt) * 2 + 0) * 32 + L];
            ull al1 = ALs[((mt * NKT + kt) * 2 + 1) * 32 + L];
            uint32_t a0h = lo32(ah0), a2h = hi32(ah0);
            uint32_t a1h = lo32(ah1), a3h = hi32(ah1);
            uint32_t a0l = lo32(al0), a2l = hi32(al0);
            uint32_t a1l = lo32(al1), a3l = hi32(al1);
            #pragma unroll
            for (int nt = 0; nt < 16; nt++) {
                int ntg = half * 16 + nt;
                ull bh = BH[(kt * 32 + ntg) * 32 + L];
                ull bl = BL[(kt * 32 + ntg) * 32 + L];
                mma16816(acc[nt], a0h, a1h, a2h, a3h, lo32(bh), hi32(bh));
                mma16816(acc[nt], a0h, a1h, a2h, a3h, lo32(bl), hi32(bl));
                mma16816(acc[nt], a0l, a1l, a2l, a3l, lo32(bh), hi32(bh));
            }
        }

        // exchange the gate-halves the partner needs
        if (half) {
            #pragma unroll
            for (int nt = 0; nt < 16; nt++)
                ZLO[(mt * 16 + nt) * 32 + L] = make_float2(acc[nt][0], acc[nt][1]);
        } else {
            #pragma unroll
            for (int nt = 0; nt < 16; nt++)
                ZHI[(mt * 16 + nt) * 32 + L] = make_float2(acc[nt][2], acc[nt][3]);
        }
        __syncthreads();

        // elementwise cell update for this lane's row (16 k-values)
        uint32_t phi[8], plo[8];
        float xn = (t + 1 < TT) ? xs[rowp * TT + t + 1] : 0.f;
        #pragma unroll
        for (int m = 0; m < 8; m++) {
            float zg0, zg1, zi0, zi1, zf0, zf1, zo0, zo1;
            if (half == 0) {
                float2 f2 = ZLO[(mt * 16 + m) * 32 + L];
                float2 o2 = ZLO[(mt * 16 + 8 + m) * 32 + L];
                zg0 = acc[m][0];     zg1 = acc[m][1];
                zi0 = acc[m + 8][0]; zi1 = acc[m + 8][1];
                zf0 = f2.x; zf1 = f2.y; zo0 = o2.x; zo1 = o2.y;
            } else {
                float2 g2 = ZHI[(mt * 16 + m) * 32 + L];
                float2 i2 = ZHI[(mt * 16 + 8 + m) * 32 + L];
                zg0 = g2.x; zg1 = g2.y; zi0 = i2.x; zi1 = i2.y;
                zf0 = acc[m][2];     zf1 = acc[m][3];
                zo0 = acc[m + 8][2]; zo1 = acc[m + 8][3];
            }
            float c0 = fmaf(cst[2 * m],     sig_a(zf0), tanh_a(zg0) * sig_a(zi0));
            float c1 = fmaf(cst[2 * m + 1], sig_a(zf1), tanh_a(zg1) * sig_a(zi1));
            cst[2 * m] = c0; cst[2 * m + 1] = c1;
            float h0 = tanh_a(c0) * sig_a(zo0);
            float h1 = tanh_a(c1) * sig_a(zo1);
            if (t == TT - 1) {
                int k0 = m * 8 + (L & 3) * 2;
                hF[k0 * MROWS + rowp] = h0;
                hF[(k0 + 1) * MROWS + rowp] = h1;
            } else {
                __nv_bfloat16 b0 = __float2bfloat16_rn(h0);
                __nv_bfloat16 b1 = __float2bfloat16_rn(h1);
                phi[m] = (uint32_t)__bfloat16_as_ushort(b0) |
                         ((uint32_t)__bfloat16_as_ushort(b1) << 16);
                __nv_bfloat16 r0 = __float2bfloat16_rn(h0 - __bfloat162float(b0));
                __nv_bfloat16 r1 = __float2bfloat16_rn(h1 - __bfloat162float(b1));
                plo[m] = (uint32_t)__bfloat16_as_ushort(r0) |
                         ((uint32_t)__bfloat16_as_ushort(r1) << 16);
            }
        }
        if (t < TT - 1) {
            #pragma unroll
            for (int ktw = 0; ktw < 4; ktw++) {
                AHs[((mt * NKT + ktw) * 2 + half) * 32 + L] =
                    (ull)phi[2 * ktw] | ((ull)phi[2 * ktw + 1] << 32);
                ALs[((mt * NKT + ktw) * 2 + half) * 32 + L] =
                    (ull)plo[2 * ktw] | ((ull)plo[2 * ktw + 1] << 32);
            }
            if ((L & 3) == 0) {
                __nv_bfloat16 xh = __float2bfloat16_rn(xn);
                float xr = xn - __bfloat162float(xh);
                uint32_t ph = (uint32_t)__bfloat16_as_ushort(xh) | (0x3F80u << 16);
                uint32_t pl = (uint32_t)__bfloat16_as_ushort(__float2bfloat16_rn(xr));
                AHs[((mt * NKT + 4) * 2 + half) * 32 + L] = (ull)ph;
                ALs[((mt * NKT + 4) * 2 + half) * 32 + L] = (ull)pl;
            }
        }
    }
    __syncthreads();

    // ---- FC head: relu(h) -> 32 relu -> 12 ----
    int l = L;
    #pragma unroll
    for (int rr = 0; rr < 8; rr++) {
        int row = w * 8 + rr;
        int n = n0 + row;
        float m = f1bs[l];
        #pragma unroll 8
        for (int j = 0; j < HH; j++)
            m = fmaf(fmaxf(hF[j * MROWS + row], 0.f), fc1s[j * 32 + l], m);
        m = fmaxf(m, 0.f);
        mids[w * 32 + l] = m;
        __syncwarp();
        if (l < NOUT) {
            float o = f2bs[l];
            #pragma unroll
            for (int q = 0; q < 32; q++)
                o = fmaf(mids[w * 32 + q], fc2s[q * NOUT + l], o);
            if (n < NN) out[(b * NOUT + l) * NN + n] = o;
        }
        __syncwarp();
    }
}

// ---------------- launch ----------------
extern "C" void kernel_launch(void* const* d_in, const int* in_sizes, int n_in,
                              void* d_out, int out_size) {
    const float* x      = (const float*)d_in[0];
    const float* lwx_W1 = (const float*)d_in[1];
    const float* lwx_b1 = (const float*)d_in[2];
    const float* lwx_W2 = (const float*)d_in[3];
    const float* lwx_b2 = (const float*)d_in[4];
    const float* lwh_W1 = (const float*)d_in[5];
    const float* lwh_b1 = (const float*)d_in[6];
    const float* lwh_W2 = (const float*)d_in[7];
    const float* lwh_b2 = (const float*)d_in[8];
    const float* lb_W1  = (const float*)d_in[9];
    const float* lb_b1  = (const float*)d_in[10];
    const float* lb_W2  = (const float*)d_in[11];
    const float* lb_b2  = (const float*)d_in[12];
    const float* fc1_W  = (const float*)d_in[13];
    const float* fc1_b  = (const float*)d_in[14];
    const float* fc2_W  = (const float*)d_in[15];
    const float* fc2_b  = (const float*)d_in[16];
    float* out = (float*)d_out;

    cudaFuncSetAttribute(k_lstm3, cudaFuncAttributeMaxDynamicSharedMemorySize, SM_TOT);

    k_meta<<<NB, EE>>>(x);
    k_hidden<<<dim3(NB, 4, 3), LHH>>>(lwx_W1, lwx_b1, lwh_W1, lwh_b1, lb_W1, lb_b1);
    k_small2<<<dim3(NB, 4, 2), HH>>>(lwx_W2, lwx_b2, lb_W2, lb_b2);
    k_wh2<<<dim3(4, 8, 4), 256>>>(lwh_W2, lwh_b2);
    k_pack3<<<NB, 256>>>();
    k_lstm3<<<dim3(NCHUNK, NB), 256, SM_TOT>>>(x, fc1_W, fc1_b, fc2_W, fc2_b, out);
}

// round 6
// speedup vs baseline: 1.4321x; 1.2673x over previous
#include <cuda_runtime.h>
#include <cuda_bf16.h>
#include <cstdint>

#define NB   64
#define TT   12
#define NN   325
#define HH   64
#define EE   32
#define LHH  128
#define NOUT 12
#define XST  97
#define MOFF 65

#define MROWS 64
#define NCHUNK 6                 // ceil(325/64)
#define NKT   5                  // k-tiles of 16 over augmented K=80

typedef unsigned long long ull;

// ---------------- device scratch ----------------
__device__ float g_meta[NB * EE];
__device__ float g_hidden[3 * 4 * NB * LHH];
__device__ float g_Wx[4 * NB * HH];
__device__ float g_bg[4 * NB * HH];
__device__ float g_Wh[4 * NB * HH * HH];
__device__ __align__(16) ulonglong2 g_WB[NB * NKT * 32 * 32];  // {hi,lo} B frags

// ---------------- activations ----------------
__device__ __forceinline__ float ex2f(float x) {
    float y; asm("ex2.approx.f32 %0,%1;" : "=f"(y) : "f"(x)); return y;
}
__device__ __forceinline__ float rcpf(float x) {
    float y; asm("rcp.approx.f32 %0,%1;" : "=f"(y) : "f"(x)); return y;
}
__device__ __forceinline__ float sig_a(float z) {
    return rcpf(1.0f + ex2f(-1.4426950408889634f * z));
}
__device__ __forceinline__ float tanh_a(float z) {
    return fmaf(-2.0f, rcpf(1.0f + ex2f(2.8853900817779268f * z)), 1.0f);
}

// ---------------- mma.sync m16n8k16 bf16 ----------------
__device__ __forceinline__ void mma16816(float* c,
    uint32_t a0, uint32_t a1, uint32_t a2, uint32_t a3,
    uint32_t b0, uint32_t b1) {
    asm volatile(
        "mma.sync.aligned.m16n8k16.row.col.f32.bf16.bf16.f32 "
        "{%0,%1,%2,%3}, {%4,%5,%6,%7}, {%8,%9}, {%0,%1,%2,%3};"
        : "+f"(c[0]), "+f"(c[1]), "+f"(c[2]), "+f"(c[3])
        : "r"(a0), "r"(a1), "r"(a2), "r"(a3), "r"(b0), "r"(b1));
}
__device__ __forceinline__ uint32_t lo32(ull v) { return (uint32_t)v; }
__device__ __forceinline__ uint32_t hi32(ull v) { return (uint32_t)(v >> 32); }
__device__ __forceinline__ uint32_t pkbf(float a, float b) {
    __nv_bfloat16 ha = __float2bfloat16_rn(a);
    __nv_bfloat16 hb = __float2bfloat16_rn(b);
    return (uint32_t)__bfloat16_as_ushort(ha) |
           ((uint32_t)__bfloat16_as_ushort(hb) << 16);
}

// ---------------- K1: meta ----------------
__global__ void k_meta(const float* __restrict__ x) {
    int b = blockIdx.x, e = threadIdx.x;
    float s = 0.f;
    #pragma unroll
    for (int t = 0; t < TT; t++)
        s += x[((size_t)(b * TT + t) * NN) * XST + MOFF + e];
    g_meta[b * EE + e] = s * (1.0f / TT);
}

// ---------------- K2: first MLP layers ----------------
__global__ void k_hidden(const float* __restrict__ xW1, const float* __restrict__ xb1,
                         const float* __restrict__ hW1, const float* __restrict__ hb1,
                         const float* __restrict__ bW1, const float* __restrict__ bb1) {
    int b = blockIdx.x, g = blockIdx.y, m = blockIdx.z;
    int l = threadIdx.x;
    const float* W1 = (m == 0) ? xW1 : (m == 1) ? hW1 : bW1;
    const float* b1 = (m == 0) ? xb1 : (m == 1) ? hb1 : bb1;
    float acc = b1[g * LHH + l];
    #pragma unroll 8
    for (int e = 0; e < EE; e++)
        acc = fmaf(g_meta[b * EE + e], W1[(g * EE + e) * LHH + l], acc);
    g_hidden[((m * 4 + g) * NB + b) * LHH + l] = fmaxf(acc, 0.f);
}

// ---------------- K3ab: Wx / bias second layers ----------------
__global__ void k_small2(const float* __restrict__ xW2, const float* __restrict__ xb2,
                         const float* __restrict__ bW2, const float* __restrict__ bb2) {
    int b = blockIdx.x, g = blockIdx.y, m2 = blockIdx.z;
    int k = threadIdx.x;
    int m = (m2 == 0) ? 0 : 2;
    const float* W2 = (m2 == 0) ? xW2 : bW2;
    const float* b2 = (m2 == 0) ? xb2 : bb2;
    const float* hid = &g_hidden[((m * 4 + g) * NB + b) * LHH];
    float acc = b2[g * HH + k];
    #pragma unroll 8
    for (int l = 0; l < LHH; l++)
        acc = fmaf(hid[l], W2[(g * LHH + l) * HH + k], acc);
    float* dst = (m2 == 0) ? g_Wx : g_bg;
    dst[(g * NB + b) * HH + k] = acc;
}

// ---------------- K3c: Wh second layer GEMM (512 CTAs) ----------------
__global__ void k_wh2(const float* __restrict__ hW2, const float* __restrict__ hb2) {
    __shared__ float hs[4][LHH];
    int kq = blockIdx.x, bt = blockIdx.y, g = blockIdx.z;
    int tid = threadIdx.x;                   // 256
    for (int i = tid; i < 4 * LHH; i += 256)
        hs[i >> 7][i & 127] = g_hidden[((4 + g) * NB + bt * 4 + (i >> 7)) * LHH + (i & 127)];
    __syncthreads();
    int k2 = kq * 512 + tid * 2;
    float2 acc[4];
    #pragma unroll
    for (int bb = 0; bb < 4; bb++) acc[bb] = make_float2(0.f, 0.f);
    #pragma unroll 8
    for (int l = 0; l < LHH; l++) {
        float2 wv = *(const float2*)&hW2[(size_t)(g * LHH + l) * 4096 + k2];
        #pragma unroll
        for (int bb = 0; bb < 4; bb++) {
            float h = hs[bb][l];
            acc[bb].x = fmaf(h, wv.x, acc[bb].x);
            acc[bb].y = fmaf(h, wv.y, acc[bb].y);
        }
    }
    float2 bias = *(const float2*)&hb2[g * 4096 + k2];
    #pragma unroll
    for (int bb = 0; bb < 4; bb++) {
        float2 v = make_float2(acc[bb].x + bias.x, acc[bb].y + bias.y);
        *(float2*)&g_Wh[(size_t)(g * NB + bt * 4 + bb) * 4096 + k2] = v;
    }
}

// ---------------- K3d: pack augmented WB into interleaved B fragments ----
__device__ __forceinline__ float fetchWB(int b, int j, int col) {
    int g = col >> 6, kk = col & 63;
    if (j < 64)  return g_Wh[((size_t)(g * NB + b) << 12) + j * 64 + kk];
    if (j == 64) return g_Wx[(g * NB + b) * HH + kk];
    if (j == 65) return g_bg[(g * NB + b) * HH + kk];
    return 0.f;
}
__global__ void k_pack3() {
    int b = blockIdx.x, kt = blockIdx.y, tid = threadIdx.x;
    for (int i = tid; i < 1024; i += 256) {
        int L = i & 31, ntg = i >> 5;
        int col = ntg * 8 + (L >> 2);
        int j0 = kt * 16 + (L & 3) * 2;
        float v00 = fetchWB(b, j0,     col);
        float v01 = fetchWB(b, j0 + 1, col);
        float v10 = fetchWB(b, j0 + 8, col);
        float v11 = fetchWB(b, j0 + 9, col);
        __nv_bfloat16 h00 = __float2bfloat16_rn(v00);
        __nv_bfloat16 h01 = __float2bfloat16_rn(v01);
        __nv_bfloat16 h10 = __float2bfloat16_rn(v10);
        __nv_bfloat16 h11 = __float2bfloat16_rn(v11);
        uint32_t p0 = (uint32_t)__bfloat16_as_ushort(h00) |
                      ((uint32_t)__bfloat16_as_ushort(h01) << 16);
        uint32_t p1 = (uint32_t)__bfloat16_as_ushort(h10) |
                      ((uint32_t)__bfloat16_as_ushort(h11) << 16);
        uint32_t q0 = pkbf(v00 - __bfloat162float(h00), v01 - __bfloat162float(h01));
        uint32_t q1 = pkbf(v10 - __bfloat162float(h10), v11 - __bfloat162float(h11));
        ulonglong2 w;
        w.x = (ull)p0 | ((ull)p1 << 32);
        w.y = (ull)q0 | ((ull)q1 << 32);
        g_WB[(size_t)b * (NKT * 1024) + kt * 1024 + i] = w;
    }
}

// ---------------- K4: HMMA LSTM recurrence + FC head ----------------
// smem byte offsets
#define SM_WB   0        // 5*32*32 ulonglong2 = 81920  (hF 16KB overlays after)
#define SM_AH   81920    // 4mt*5kt*32 ulonglong2 = 10240 (FC overlay after loop)
#define SM_AL   92160    // 10240
#define SM_XS   102400   // 64*12*4 = 3072
#define SM_F1B  105472   // 128
#define SM_F2B  105600   // 64
#define SM_MID  105664   // 1024
#define SM_TOT  106688
#define SM_FC1  SM_AH            // overlay (post-loop)
#define SM_FC2  (SM_AH + 8192)   // overlay

__global__ __launch_bounds__(256, 2)
void k_lstm3(const float* __restrict__ x,
             const float* __restrict__ fc1W, const float* __restrict__ fc1b,
             const float* __restrict__ fc2W, const float* __restrict__ fc2b,
             float* __restrict__ out) {
    extern __shared__ char smc[];
    ulonglong2* WB  = (ulonglong2*)(smc + SM_WB);
    ulonglong2* AH2 = (ulonglong2*)(smc + SM_AH);
    ulonglong2* AL2 = (ulonglong2*)(smc + SM_AL);
    float* xs   = (float*)(smc + SM_XS);
    float* f1bs = (float*)(smc + SM_F1B);
    float* f2bs = (float*)(smc + SM_F2B);
    float* mids = (float*)(smc + SM_MID);
    float* hF   = (float*)(smc + SM_WB);    // overlay

    int chunk = blockIdx.x, b = blockIdx.y;
    int tid = threadIdx.x;
    int w = tid >> 5, L = tid & 31;
    int mt = w >> 1, half = w & 1;
    int n0 = chunk * MROWS;
    int r0 = mt * 16 + (L >> 2);            // chunk-local row (slot 0); slot1 = +8

    // ---- stage ----
    {
        const uint4* src = (const uint4*)&g_WB[(size_t)b * (NKT * 1024)];
        uint4* dst = (uint4*)WB;
        for (int i = tid; i < NKT * 1024; i += 256) dst[i] = src[i];
    }
    for (int i = tid; i < 2 * 4 * NKT * 32; i += 256) {
        ulonglong2 z; z.x = 0ull; z.y = 0ull;
        ((ulonglong2*)AH2)[i] = z;          // covers AH2 then AL2 (contiguous)
    }
    for (int i = tid; i < MROWS * TT; i += 256) {
        int r = i / TT, t = i % TT;
        int n = n0 + r;
        xs[r * TT + t] = (n < NN) ? x[((size_t)(b * TT + t) * NN + n) * XST] : 0.f;
    }
    if (tid < 32) f1bs[tid] = fc1b[tid];
    if (tid < NOUT) f2bs[tid] = fc2b[tid];
    __syncthreads();

    // seed augmented kt=4 tile with (x_0, 1.0); half==0 warps cover both slots
    if (half == 0 && (L & 3) == 0) {
        ull* aw = (ull*)&AH2[(mt * NKT + 4) * 32 + L];
        ull* al = (ull*)&AL2[(mt * NKT + 4) * 32 + L];
        #pragma unroll
        for (int s = 0; s < 2; s++) {
            float xv = xs[(r0 + s * 8) * TT];
            __nv_bfloat16 xh = __float2bfloat16_rn(xv);
            aw[s] = (ull)((uint32_t)__bfloat16_as_ushort(xh) | (0x3F80u << 16));
            al[s] = (ull)pkbf(xv - __bfloat162float(xh), 0.f);
        }
    }

    float cst[16];
    #pragma unroll
    for (int i = 0; i < 16; i++) cst[i] = 0.f;

    for (int t = 0; t < TT; t++) {
        __syncthreads();                     // A frags (h_{t-1}, x_t) visible

        float acc[4][4][4];
        #pragma unroll
        for (int g = 0; g < 4; g++)
            #pragma unroll
            for (int nl = 0; nl < 4; nl++)
                #pragma unroll
                for (int i = 0; i < 4; i++) acc[g][nl][i] = 0.f;

        #pragma unroll
        for (int kt = 0; kt < NKT; kt++) {
            if (t == 0 && kt < 4) continue;  // h=0 at t=0
            ulonglong2 ah = AH2[(mt * NKT + kt) * 32 + L];
            ulonglong2 al = AL2[(mt * NKT + kt) * 32 + L];
            uint32_t a0h = lo32(ah.x), a2h = hi32(ah.x);
            uint32_t a1h = lo32(ah.y), a3h = hi32(ah.y);
            uint32_t a0l = lo32(al.x), a2l = hi32(al.x);
            uint32_t a1l = lo32(al.y), a3l = hi32(al.y);
            #pragma unroll
            for (int g = 0; g < 4; g++) {
                #pragma unroll
                for (int nl = 0; nl < 4; nl++) {
                    int ntg = g * 8 + half * 4 + nl;
                    ulonglong2 bw = WB[(kt * 32 + ntg) * 32 + L];
                    mma16816(acc[g][nl], a0h, a1h, a2h, a3h, lo32(bw.x), hi32(bw.x));
                    mma16816(acc[g][nl], a0h, a1h, a2h, a3h, lo32(bw.y), hi32(bw.y));
                    mma16816(acc[g][nl], a0l, a1l, a2l, a3l, lo32(bw.x), hi32(bw.x));
                }
            }
        }
        __syncthreads();                     // all A/B reads done before rewrites

        // elementwise: this lane owns all 4 gates for 2 rows x 8 k-cols
        float hv[4][2][2];                   // [nl][s][q]
        #pragma unroll
        for (int nl = 0; nl < 4; nl++)
            #pragma unroll
            for (int s = 0; s < 2; s++)
                #pragma unroll
                for (int q = 0; q < 2; q++) {
                    int ci = s * 2 + q;
                    float zg = acc[0][nl][ci];
                    float zi = acc[1][nl][ci];
                    float zf = acc[2][nl][ci];
                    float zo = acc[3][nl][ci];
                    int cix = nl * 4 + ci;
                    float cv = fmaf(cst[cix], sig_a(zf), tanh_a(zg) * sig_a(zi));
                    cst[cix] = cv;
                    hv[nl][s][q] = tanh_a(cv) * sig_a(zo);
                }

        if (t == TT - 1) {
            #pragma unroll
            for (int nl = 0; nl < 4; nl++)
                #pragma unroll
                for (int s = 0; s < 2; s++)
                    #pragma unroll
                    for (int q = 0; q < 2; q++) {
                        int k = half * 32 + nl * 8 + (L & 3) * 2 + q;
                        hF[k * MROWS + r0 + s * 8] = hv[nl][s][q];
                    }
        } else {
            // write A fragments for t+1 (this warp owns kt = 2*half, 2*half+1)
            #pragma unroll
            for (int ktl = 0; ktl < 2; ktl++) {
                int kt = 2 * half + ktl;
                ull* aw = (ull*)&AH2[(mt * NKT + kt) * 32 + L];
                ull* al = (ull*)&AL2[(mt * NKT + kt) * 32 + L];
                #pragma unroll
                for (int s = 0; s < 2; s++) {
                    float e0 = hv[2 * ktl][s][0],     e1 = hv[2 * ktl][s][1];
                    float o0 = hv[2 * ktl + 1][s][0], o1 = hv[2 * ktl + 1][s][1];
                    uint32_t phE = pkbf(e0, e1), phO = pkbf(o0, o1);
                    aw[s] = (ull)phE | ((ull)phO << 32);
                    __nv_bfloat16 be0 = __float2bfloat16_rn(e0);
                    __nv_bfloat16 be1 = __float2bfloat16_rn(e1);
                    __nv_bfloat16 bo0 = __float2bfloat16_rn(o0);
                    __nv_bfloat16 bo1 = __float2bfloat16_rn(o1);
                    uint32_t plE = pkbf(e0 - __bfloat162float(be0), e1 - __bfloat162float(be1));
                    uint32_t plO = pkbf(o0 - __bfloat162float(bo0), o1 - __bfloat162float(bo1));
                    al[s] = (ull)plE | ((ull)plO << 32);
                }
            }
            if (half == 0 && (L & 3) == 0) {  // x_{t+1} augment
                ull* aw = (ull*)&AH2[(mt * NKT + 4) * 32 + L];
                ull* al = (ull*)&AL2[(mt * NKT + 4) * 32 + L];
                #pragma unroll
                for (int s = 0; s < 2; s++) {
                    float xv = xs[(r0 + s * 8) * TT + t + 1];
                    __nv_bfloat16 xh = __float2bfloat16_rn(xv);
                    aw[s] = (ull)((uint32_t)__bfloat16_as_ushort(xh) | (0x3F80u << 16));
                    al[s] = (ull)pkbf(xv - __bfloat162float(xh), 0.f);
                }
            }
        }
    }
    __syncthreads();

    // ---- load FC weights into overlay (A frags dead now) ----
    float* fc1s = (float*)(smc + SM_FC1);
    float* fc2s = (float*)(smc + SM_FC2);
    for (int i = tid; i < HH * 32; i += 256) fc1s[i] = fc1W[i];
    for (int i = tid; i < 32 * NOUT; i += 256) fc2s[i] = fc2W[i];
    __syncthreads();

    // ---- FC head: relu(h) -> 32 relu -> 12 ----
    #pragma unroll
    for (int rr = 0; rr < 8; rr++) {
        int row = w * 8 + rr;
        int n = n0 + row;
        float m = f1bs[L];
        #pragma unroll 8
        for (int j = 0; j < HH; j++)
            m = fmaf(fmaxf(hF[j * MROWS + row], 0.f), fc1s[j * 32 + L], m);
        m = fmaxf(m, 0.f);
        mids[w * 32 + L] = m;
        __syncwarp();
        if (L < NOUT) {
            float o = f2bs[L];
            #pragma unroll
            for (int q = 0; q < 32; q++)
                o = fmaf(mids[w * 32 + q], fc2s[q * NOUT + L], o);
            if (n < NN) out[(b * NOUT + L) * NN + n] = o;
        }
        __syncwarp();
    }
}

// ---------------- launch ----------------
extern "C" void kernel_launch(void* const* d_in, const int* in_sizes, int n_in,
                              void* d_out, int out_size) {
    const float* x      = (const float*)d_in[0];
    const float* lwx_W1 = (const float*)d_in[1];
    const float* lwx_b1 = (const float*)d_in[2];
    const float* lwx_W2 = (const float*)d_in[3];
    const float* lwx_b2 = (const float*)d_in[4];
    const float* lwh_W1 = (const float*)d_in[5];
    const float* lwh_b1 = (const float*)d_in[6];
    const float* lwh_W2 = (const float*)d_in[7];
    const float* lwh_b2 = (const float*)d_in[8];
    const float* lb_W1  = (const float*)d_in[9];
    const float* lb_b1  = (const float*)d_in[10];
    const float* lb_W2  = (const float*)d_in[11];
    const float* lb_b2  = (const float*)d_in[12];
    const float* fc1_W  = (const float*)d_in[13];
    const float* fc1_b  = (const float*)d_in[14];
    const float* fc2_W  = (const float*)d_in[15];
    const float* fc2_b  = (const float*)d_in[16];
    float* out = (float*)d_out;

    cudaFuncSetAttribute(k_lstm3, cudaFuncAttributeMaxDynamicSharedMemorySize, SM_TOT);

    k_meta<<<NB, EE>>>(x);
    k_hidden<<<dim3(NB, 4, 3), LHH>>>(lwx_W1, lwx_b1, lwh_W1, lwh_b1, lb_W1, lb_b1);
    k_small2<<<dim3(NB, 4, 2), HH>>>(lwx_W2, lwx_b2, lb_W2, lb_b2);
    k_wh2<<<dim3(8, 16, 4), 256>>>(lwh_W2, lwh_b2);
    k_pack3<<<dim3(NB, NKT), 256>>>();
    k_lstm3<<<dim3(NCHUNK, NB), 256, SM_TOT>>>(x, fc1_W, fc1_b, fc2_W, fc2_b, out);
}